// round 10
// baseline (speedup 1.0000x reference)
#include <cuda_runtime.h>
#include <cuda_bf16.h>
#include <cstdint>

#define NN 8192
#define LEAK 0.7f

// ---------------- global scratch ----------------
__device__ __align__(16) __nv_bfloat16 gUh[NN * 64], gUl[NN * 64];
__device__ __align__(16) __nv_bfloat16 gVh[NN * 64], gVl[NN * 64];
__device__ __align__(16) __nv_bfloat16 gVch[(NN + 64) * 64], gVcl[(NN + 64) * 64];
__device__ __align__(16) __nv_bfloat16 gEh[128 * 128 * 64], gEl[128 * 128 * 64]; // [c][dcat][r]
__device__ int g_idx[NN + 64];
__device__ int g_cnt;

// ---------------- helpers ----------------
__device__ __forceinline__ uint32_t smem_u32(const void* p) {
    uint32_t a;
    asm("{ .reg .u64 t; cvta.to.shared.u64 t, %1; cvt.u32.u64 %0, t; }" : "=r"(a) : "l"(p));
    return a;
}
#define LDSM4(R0, R1, R2, R3, A)                                                 \
    asm volatile("ldmatrix.sync.aligned.m8n8.x4.shared.b16 {%0,%1,%2,%3}, [%4];" \
                 : "=r"(R0), "=r"(R1), "=r"(R2), "=r"(R3) : "r"(A))
#define MMA_BF16(c, a0, a1, a2, a3, b0, b1)                                   \
    asm volatile("mma.sync.aligned.m16n8k16.row.col.f32.bf16.bf16.f32 "       \
                 "{%0,%1,%2,%3},{%4,%5,%6,%7},{%8,%9},{%0,%1,%2,%3};"         \
                 : "+f"((c)[0]), "+f"((c)[1]), "+f"((c)[2]), "+f"((c)[3])     \
                 : "r"(a0), "r"(a1), "r"(a2), "r"(a3), "r"(b0), "r"(b1))
#define CP16(dst, src) \
    asm volatile("cp.async.cg.shared.global [%0], [%1], 16;" :: "r"(dst), "l"(src))
#define CP_COMMIT() asm volatile("cp.async.commit_group;" ::: "memory")
#define WG0() asm volatile("cp.async.wait_group 0;" ::: "memory")
#define WG1() asm volatile("cp.async.wait_group 1;" ::: "memory")

__device__ __forceinline__ void split2(float x, __nv_bfloat16& h, __nv_bfloat16& l) {
    h = __float2bfloat16(x);
    l = __float2bfloat16(x - __bfloat162float(h));
}

// ---------------- prep: scan (block 512) + V = U @ W (blocks 0..511) ----------
__global__ void __launch_bounds__(256) prep_se(const float* __restrict__ U,
                                               const float* __restrict__ W,
                                               const float* __restrict__ prof) {
    __shared__ float Wt[64 * 68];
    __shared__ float Ur[16 * 64];
    __shared__ int wsum[8];
    int tid = threadIdx.x;

    if (blockIdx.x == 512) {
        // union active-row scan, 32 rows/thread
        int base = tid * 32;
        uint32_t m = 0;
        int local = 0;
#pragma unroll 8
        for (int q = 0; q < 32; q++) {
            int i = base + q;
            int a = (prof[i] > LEAK) || (prof[NN + i] > LEAK);
            m |= ((uint32_t)a) << q;
            local += a;
        }
        int lane = tid & 31, wid = tid >> 5;
        int inc = local;
#pragma unroll
        for (int d = 1; d < 32; d <<= 1) {
            int v = __shfl_up_sync(~0u, inc, d);
            if (lane >= d) inc += v;
        }
        if (lane == 31) wsum[wid] = inc;
        __syncthreads();
        if (wid == 0 && lane < 8) {
            int v = wsum[lane];
#pragma unroll
            for (int d = 1; d < 8; d <<= 1) {
                int u = __shfl_up_sync(0xffu, v, d);
                if (lane >= d) v += u;
            }
            wsum[lane] = v;
        }
        __syncthreads();
        int excl = inc - local + (wid > 0 ? wsum[wid - 1] : 0);
        for (int q = 0; q < 32; q++)
            if ((m >> q) & 1) g_idx[excl++] = base + q;
        if (tid == 255) {
            g_cnt = excl;
            for (int p = excl; p < ((excl + 63) & ~63); p++) g_idx[p] = -1;
        }
        return;
    }

    int row0 = blockIdx.x * 16;
    for (int i = tid; i < 4096; i += 256) {
        int c = i & 63, e = i >> 6;
        Wt[c * 68 + e] = W[e * 64 + c];
    }
    for (int i = tid; i < 1024; i += 256) Ur[i] = U[row0 * 64 + i];
    __syncthreads();
    int c = tid & 63, rq = tid >> 6;
    float acc[4] = {0.f, 0.f, 0.f, 0.f};
    const float4* wt4 = (const float4*)(Wt + c * 68);
#pragma unroll
    for (int e4 = 0; e4 < 16; e4++) {
        float4 wv = wt4[e4];
#pragma unroll
        for (int q = 0; q < 4; q++) {
            float4 uv = *(const float4*)(Ur + (rq + 4 * q) * 64 + e4 * 4);
            acc[q] += uv.x * wv.x + uv.y * wv.y + uv.z * wv.z + uv.w * wv.w;
        }
    }
#pragma unroll
    for (int q = 0; q < 4; q++) {
        int r = rq + 4 * q, row = row0 + r;
        __nv_bfloat16 h, lo;
        split2(Ur[r * 64 + c], h, lo);
        gUh[row * 64 + c] = h;
        gUl[row * 64 + c] = lo;
        split2(acc[q], h, lo);
        gVh[row * 64 + c] = h;
        gVl[row * 64 + c] = lo;
    }
}

// ---------------- prep 2: compacted V + gated E tiles ----------------
__global__ void __launch_bounds__(256) prep_effV(const float* __restrict__ S,
                                                 const float* __restrict__ prof) {
    int c = blockIdx.x, tid = threadIdx.x;
    int nt = (g_cnt + 63) >> 6;
    if (c >= nt) return;
    __shared__ float es[64 * 130];
    __shared__ int sidx[64];
    __shared__ float sg[2][64];
    if (tid < 64) {
        int gi = g_idx[c * 64 + tid];
        sidx[tid] = gi;
        float g0 = 0.f, g1 = 0.f;
        if (gi >= 0) {
            g0 = prof[gi] - LEAK;        g0 = g0 > 0.f ? g0 : 0.f;
            g1 = prof[NN + gi] - LEAK;   g1 = g1 > 0.f ? g1 : 0.f;
        }
        sg[0][tid] = g0;
        sg[1][tid] = g1;
    }
    __syncthreads();
    for (int idx = tid; idx < 8192; idx += 256) {
        int r = idx >> 7, dc = idx & 127;
        int b = dc >> 6, d = dc & 63;
        int gi = sidx[r];
        es[r * 130 + dc] = (gi >= 0) ? S[((size_t)b * NN + gi) * 64 + d] * sg[b][r] : 0.f;
    }
    for (int idx = tid; idx < 2048; idx += 256) {
        int r = idx >> 5, k2 = idx & 31;
        int gi = sidx[r];
        uint32_t vh = 0u, vl = 0u;
        if (gi >= 0) {
            vh = ((const uint32_t*)gVh)[gi * 32 + k2];
            vl = ((const uint32_t*)gVl)[gi * 32 + k2];
        }
        ((uint32_t*)gVch)[(c * 64 + r) * 32 + k2] = vh;
        ((uint32_t*)gVcl)[(c * 64 + r) * 32 + k2] = vl;
    }
    __syncthreads();
    int base = c * 8192;
    for (int idx = tid; idx < 8192; idx += 256) {
        int dc = idx >> 6, r = idx & 63;
        float x = es[r * 130 + dc];
        __nv_bfloat16 h, lo;
        split2(x, h, lo);
        gEh[base + dc * 64 + r] = h;
        gEl[base + dc * 64 + r] = lo;
    }
}

// ---------------- main: triple-buffered, interleaved G2(t)/G1(t+1) ----------------
#define SM_U 0u
#define SM_STG 18432u
#define STG_SZ 55552u   // V(18432) + E(36864) + idx(256)
#define SM_TOTAL (18432u + 3u * 55552u)   // 185088

__device__ __forceinline__ void stage_load(uint32_t stg, int t, int tid) {
#pragma unroll
    for (int idx = tid; idx < 1024; idx += 256) {
        int h = idx >> 9, rem = idx & 511, r = rem >> 3, c = rem & 7;
        uint32_t dst = stg + h * 9216u + r * 144u + c * 16u;
        const char* src = (const char*)(h ? gVcl : gVch) + ((size_t)t * 4096 + r * 64 + c * 8) * 2;
        CP16(dst, src);
    }
#pragma unroll
    for (int idx = tid; idx < 2048; idx += 256) {
        int h = idx >> 10, rem = idx & 1023, r = rem >> 3, c = rem & 7;
        uint32_t dst = stg + 18432u + h * 18432u + r * 144u + c * 16u;
        const char* src = (const char*)(h ? gEl : gEh) + ((size_t)t * 8192 + r * 64 + c * 8) * 2;
        CP16(dst, src);
    }
    if (tid < 16)
        CP16(stg + 55296u + tid * 16u, (const char*)(g_idx + t * 64) + tid * 16);
}

__global__ void __launch_bounds__(256, 1) dyadic_mma(const float* __restrict__ S,
                                                     const float* __restrict__ bias_p,
                                                     float* __restrict__ out) {
    extern __shared__ char sm[];
    const uint32_t sb = smem_u32(sm);
    const int tid = threadIdx.x, w = tid >> 5, lane = tid & 31;
    const int jc = blockIdx.x;
    const float bias = bias_p[0];
    const int nt = (g_cnt + 63) >> 6;

    const int g = lane >> 2, tig = lane & 3;
    const int a_r = lane & 15;
    const int a_c = (lane & 16) ? 8 : 0;
    const int b_r = (lane & 7) + ((lane & 16) ? 8 : 0);
    const int b_c = (lane & 8) ? 8 : 0;

    const int mj = w & 3;   // j slice [16*mj, +16)
    const int nw = w >> 2;  // i slice [32*nw, +32)

    // stage resident U tile
    {
        const uint4* sh = (const uint4*)gUh + jc * 512;
        const uint4* sl = (const uint4*)gUl + jc * 512;
        for (int idx = tid; idx < 512; idx += 256) {
            int r = idx >> 3, c = idx & 7;
            *(uint4*)(sm + SM_U + r * 144 + c * 16) = sh[idx];
            *(uint4*)(sm + SM_U + 9216 + r * 144 + c * 16) = sl[idx];
        }
    }
    stage_load(sb + SM_STG, 0, tid);
    CP_COMMIT();
    if (nt > 1) {
        stage_load(sb + SM_STG + STG_SZ, 1, tid);
        CP_COMMIT();
        WG1();
    } else {
        WG0();
    }
    __syncthreads();  // U + stage0 visible

    float d2[16][4];
#pragma unroll
    for (int nb = 0; nb < 16; nb++)
#pragma unroll
        for (int q = 0; q < 4; q++) d2[nb][q] = 0.f;

    // hoist loop-invariant U A-fragments
    uint32_t uah[4][4], ual[4][4];
    {
        const uint32_t ua = sb + SM_U + (16 * mj + a_r) * 144 + a_c * 2;
#pragma unroll
        for (int ks = 0; ks < 4; ks++) {
            LDSM4(uah[ks][0], uah[ks][1], uah[ks][2], uah[ks][3], ua + ks * 32);
            LDSM4(ual[ks][0], ual[ks][1], ual[ks][2], ual[ks][3], ua + 9216u + ks * 32);
        }
    }

    uint32_t pah[2][4], pal[2][4];

    // -------- GEMM1(0) + epilogue -> P(0) fragments --------
    {
        const uint32_t stg0 = sb + SM_STG;
        float c1[4][4];
#pragma unroll
        for (int nb = 0; nb < 4; nb++)
#pragma unroll
            for (int q = 0; q < 4; q++) c1[nb][q] = 0.f;
        const uint32_t vbh = stg0 + (32 * nw + b_r) * 144 + b_c * 2;
#pragma unroll
        for (int ks = 0; ks < 4; ks++) {
            uint32_t bh[8], bl[8];
#pragma unroll
            for (int p = 0; p < 2; p++) {
                LDSM4(bh[4 * p], bh[4 * p + 1], bh[4 * p + 2], bh[4 * p + 3],
                      vbh + p * 16 * 144 + ks * 32);
                LDSM4(bl[4 * p], bl[4 * p + 1], bl[4 * p + 2], bl[4 * p + 3],
                      vbh + 9216u + p * 16 * 144 + ks * 32);
            }
#pragma unroll
            for (int nb = 0; nb < 4; nb++) {
                int bi = (nb >> 1) * 4 + (nb & 1) * 2;
                MMA_BF16(c1[nb], uah[ks][0], uah[ks][1], uah[ks][2], uah[ks][3], bh[bi], bh[bi + 1]);
                MMA_BF16(c1[nb], uah[ks][0], uah[ks][1], uah[ks][2], uah[ks][3], bl[bi], bl[bi + 1]);
                MMA_BF16(c1[nb], ual[ks][0], ual[ks][1], ual[ks][2], ual[ks][3], bh[bi], bh[bi + 1]);
            }
        }
        // epilogue
#pragma unroll
        for (int nb = 0; nb < 4; nb++) {
            uint32_t i0, i1;
            asm volatile("ld.shared.v2.u32 {%0,%1}, [%2];" : "=r"(i0), "=r"(i1)
                         : "r"(stg0 + 55296u + (uint32_t)(32 * nw + 8 * nb + 2 * tig) * 4u));
            float tv[4];
#pragma unroll
            for (int q = 0; q < 4; q++) {
                float x = c1[nb][q] + bias;
                float s = __fdividef(1.f, 1.f + __expf(-x));
                int gi = (int)((q & 1) ? i1 : i0);
                int jg = 64 * jc + 16 * mj + g + ((q & 2) ? 8 : 0);
                if (gi == jg) s = 0.f;
                tv[q] = s;
            }
            __nv_bfloat16 h0, l0, h1, l1, h2, l2, h3, l3;
            split2(tv[0], h0, l0); split2(tv[1], h1, l1);
            split2(tv[2], h2, l2); split2(tv[3], h3, l3);
            int ks2 = nb >> 1, ai = 2 * (nb & 1);
            pah[ks2][ai]     = (uint32_t)__bfloat16_as_ushort(h0) | ((uint32_t)__bfloat16_as_ushort(h1) << 16);
            pah[ks2][ai + 1] = (uint32_t)__bfloat16_as_ushort(h2) | ((uint32_t)__bfloat16_as_ushort(h3) << 16);
            pal[ks2][ai]     = (uint32_t)__bfloat16_as_ushort(l0) | ((uint32_t)__bfloat16_as_ushort(l1) << 16);
            pal[ks2][ai + 1] = (uint32_t)__bfloat16_as_ushort(l2) | ((uint32_t)__bfloat16_as_ushort(l3) << 16);
        }
    }

    int b3 = 0, b3n = 1, b3nn = 2;
    for (int t = 0; t < nt; t++) {
        const uint32_t bufG2 = sb + SM_STG + (uint32_t)b3 * STG_SZ;
        const uint32_t bufG1 = sb + SM_STG + (uint32_t)b3n * STG_SZ;
        __syncthreads();  // all warps done reading buffer b3nn (= G2(t-1)'s stage)

        if (t + 2 < nt) {
            stage_load(sb + SM_STG + (uint32_t)b3nn * STG_SZ, t + 2, tid);
            CP_COMMIT();
            WG1();   // stage t+1 complete (only cp(t+2) outstanding)
        } else {
            WG0();   // drain remaining
        }

        const bool doG1 = (t + 1 < nt);
        float c1[4][4];
#pragma unroll
        for (int nb = 0; nb < 4; nb++)
#pragma unroll
            for (int q = 0; q < 4; q++) c1[nb][q] = 0.f;

        const uint32_t vbh = bufG1 + (32 * nw + b_r) * 144 + b_c * 2;
        const uint32_t eb = bufG2 + 18432u + b_r * 144u + b_c * 2u + (uint32_t)(64 * nw);

        // ---- merged: interleave GEMM2(t) with GEMM1(t+1) ----
#pragma unroll
        for (int ks = 0; ks < 4; ks++) {
            uint32_t g1bh[8], g1bl[8];
            if (doG1) {
#pragma unroll
                for (int p = 0; p < 2; p++) {
                    LDSM4(g1bh[4 * p], g1bh[4 * p + 1], g1bh[4 * p + 2], g1bh[4 * p + 3],
                          vbh + p * 16 * 144 + ks * 32);
                    LDSM4(g1bl[4 * p], g1bl[4 * p + 1], g1bl[4 * p + 2], g1bl[4 * p + 3],
                          vbh + 9216u + p * 16 * 144 + ks * 32);
                }
            }
#pragma unroll
            for (int pp = 0; pp < 4; pp++) {
                // G2 group gi2 = ks*4+pp
                int gi2 = ks * 4 + pp;
                int ks2 = gi2 >> 3, p = gi2 & 7;
                uint32_t bh[4], bl[4];
                uint32_t ea = eb + p * 16 * 144 + ks2 * 32;
                LDSM4(bh[0], bh[1], bh[2], bh[3], ea);
                LDSM4(bl[0], bl[1], bl[2], bl[3], ea + 18432u);
#pragma unroll
                for (int blk = 0; blk < 2; blk++) {
                    int nb = 2 * p + blk;
                    MMA_BF16(d2[nb], pah[ks2][0], pah[ks2][1], pah[ks2][2], pah[ks2][3],
                             bh[2 * blk], bh[2 * blk + 1]);
                    MMA_BF16(d2[nb], pah[ks2][0], pah[ks2][1], pah[ks2][2], pah[ks2][3],
                             bl[2 * blk], bl[2 * blk + 1]);
                    MMA_BF16(d2[nb], pal[ks2][0], pal[ks2][1], pal[ks2][2], pal[ks2][3],
                             bh[2 * blk], bh[2 * blk + 1]);
                }
                // G1: 3 MMAs for nb = pp (per-accumulator order hh, hl, lh preserved)
                if (doG1) {
                    int bi = (pp >> 1) * 4 + (pp & 1) * 2;
                    MMA_BF16(c1[pp], uah[ks][0], uah[ks][1], uah[ks][2], uah[ks][3],
                             g1bh[bi], g1bh[bi + 1]);
                    MMA_BF16(c1[pp], uah[ks][0], uah[ks][1], uah[ks][2], uah[ks][3],
                             g1bl[bi], g1bl[bi + 1]);
                    MMA_BF16(c1[pp], ual[ks][0], ual[ks][1], ual[ks][2], ual[ks][3],
                             g1bh[bi], g1bh[bi + 1]);
                }
            }
        }

        // ---- epilogue: c1 -> P(t+1) fragments ----
        if (doG1) {
#pragma unroll
            for (int nb = 0; nb < 4; nb++) {
                uint32_t i0, i1;
                asm volatile("ld.shared.v2.u32 {%0,%1}, [%2];" : "=r"(i0), "=r"(i1)
                             : "r"(bufG1 + 55296u + (uint32_t)(32 * nw + 8 * nb + 2 * tig) * 4u));
                float tv[4];
#pragma unroll
                for (int q = 0; q < 4; q++) {
                    float x = c1[nb][q] + bias;
                    float s = __fdividef(1.f, 1.f + __expf(-x));
                    int gi = (int)((q & 1) ? i1 : i0);
                    int jg = 64 * jc + 16 * mj + g + ((q & 2) ? 8 : 0);
                    if (gi == jg) s = 0.f;
                    tv[q] = s;
                }
                __nv_bfloat16 h0, l0, h1, l1, h2, l2, h3, l3;
                split2(tv[0], h0, l0); split2(tv[1], h1, l1);
                split2(tv[2], h2, l2); split2(tv[3], h3, l3);
                int ks2 = nb >> 1, ai = 2 * (nb & 1);
                pah[ks2][ai]     = (uint32_t)__bfloat16_as_ushort(h0) | ((uint32_t)__bfloat16_as_ushort(h1) << 16);
                pah[ks2][ai + 1] = (uint32_t)__bfloat16_as_ushort(h2) | ((uint32_t)__bfloat16_as_ushort(h3) << 16);
                pal[ks2][ai]     = (uint32_t)__bfloat16_as_ushort(l0) | ((uint32_t)__bfloat16_as_ushort(l1) << 16);
                pal[ks2][ai + 1] = (uint32_t)__bfloat16_as_ushort(l2) | ((uint32_t)__bfloat16_as_ushort(l3) << 16);
            }
        }

        int tmp = b3;
        b3 = b3n; b3n = b3nn; b3nn = tmp;
    }

    // ---- cross-warp K reduction (nw pairs) + epilogue store ----
    __syncthreads();
    float* red = (float*)(sm + SM_STG);
    if (nw == 1) {
#pragma unroll
        for (int nb = 0; nb < 16; nb++)
#pragma unroll
            for (int q = 0; q < 4; q++)
                red[(mj * 64 + nb * 4 + q) * 32 + lane] = d2[nb][q];
    }
    __syncthreads();
    if (nw == 0) {
#pragma unroll
        for (int nb = 0; nb < 16; nb++)
#pragma unroll
            for (int q = 0; q < 4; q++)
                d2[nb][q] += red[(mj * 64 + nb * 4 + q) * 32 + lane];
#pragma unroll
        for (int nb = 0; nb < 16; nb++) {
            int b = nb >> 3, d = 8 * (nb & 7) + 2 * tig;
#pragma unroll
            for (int half = 0; half < 2; half++) {
                int j = 64 * jc + 16 * mj + g + 8 * half;
                size_t off = ((size_t)(b * NN + j)) * 64 + d;
                float2 sv = *(const float2*)(S + off);
                float2 ov;
                ov.x = sv.x + d2[nb][2 * half + 0];
                ov.y = sv.y + d2[nb][2 * half + 1];
                *(float2*)(out + off) = ov;
            }
        }
    }
}

extern "C" void kernel_launch(void* const* d_in, const int* in_sizes, int n_in,
                              void* d_out, int out_size) {
    const float* S    = (const float*)d_in[0];  // task_states   [2,8192,64]
    const float* prof = (const float*)d_in[1];  // proficiency   [2,8192]
    const float* U    = (const float*)d_in[2];  // task_embeddings [8192,64]
    const float* W    = (const float*)d_in[3];  // bilinear_weight [1,64,64]
    const float* bias = (const float*)d_in[4];  // bilinear_bias  [1]
    float* out = (float*)d_out;

    prep_se<<<513, 256>>>(U, W, prof);
    prep_effV<<<128, 256>>>(S, prof);

    cudaFuncSetAttribute(dyadic_mma, cudaFuncAttributeMaxDynamicSharedMemorySize, SM_TOTAL);
    dyadic_mma<<<128, 256, SM_TOTAL>>>(S, bias, out);
}

// round 11
// speedup vs baseline: 1.4905x; 1.4905x over previous
#include <cuda_runtime.h>
#include <cuda_bf16.h>
#include <cstdint>

#define NN 8192
#define LEAK 0.7f

// ---------------- global scratch ----------------
__device__ __align__(16) __nv_bfloat16 gUh[NN * 64], gUl[NN * 64];
__device__ __align__(16) __nv_bfloat16 gVh[NN * 64], gVl[NN * 64];
__device__ __align__(16) __nv_bfloat16 gVch[2][(NN + 64) * 64], gVcl[2][(NN + 64) * 64];
__device__ __align__(16) __nv_bfloat16 gEh[2][128 * 64 * 64], gEl[2][128 * 64 * 64]; // [b][c][d][i]
__device__ int g_idx[2][NN + 64];
__device__ int g_cnt[2];

// ---------------- helpers ----------------
__device__ __forceinline__ uint32_t smem_u32(const void* p) {
    uint32_t a;
    asm("{ .reg .u64 t; cvta.to.shared.u64 t, %1; cvt.u32.u64 %0, t; }" : "=r"(a) : "l"(p));
    return a;
}
#define LDSM4(R0, R1, R2, R3, A)                                                 \
    asm volatile("ldmatrix.sync.aligned.m8n8.x4.shared.b16 {%0,%1,%2,%3}, [%4];" \
                 : "=r"(R0), "=r"(R1), "=r"(R2), "=r"(R3) : "r"(A))
#define MMA_BF16(c, a0, a1, a2, a3, b0, b1)                                   \
    asm volatile("mma.sync.aligned.m16n8k16.row.col.f32.bf16.bf16.f32 "       \
                 "{%0,%1,%2,%3},{%4,%5,%6,%7},{%8,%9},{%0,%1,%2,%3};"         \
                 : "+f"((c)[0]), "+f"((c)[1]), "+f"((c)[2]), "+f"((c)[3])     \
                 : "r"(a0), "r"(a1), "r"(a2), "r"(a3), "r"(b0), "r"(b1))
#define CP16(dst, src) \
    asm volatile("cp.async.cg.shared.global [%0], [%1], 16;" :: "r"(dst), "l"(src))
#define CP_COMMIT() asm volatile("cp.async.commit_group;" ::: "memory")
#define CP_WAIT0()  asm volatile("cp.async.wait_group 0;" ::: "memory")

__device__ __forceinline__ void split2(float x, __nv_bfloat16& h, __nv_bfloat16& l) {
    h = __float2bfloat16(x);
    l = __float2bfloat16(x - __bfloat162float(h));
}

// ---------------- prep: embed (blocks 0..511) + per-batch scans (block 512) ----
__global__ void __launch_bounds__(256) prep_se(const float* __restrict__ U,
                                               const float* __restrict__ W,
                                               const float* __restrict__ prof) {
    __shared__ float Wt[64 * 68];
    __shared__ float Ur[16 * 64];
    __shared__ int wsum[8];
    int tid = threadIdx.x;

    if (blockIdx.x == 512) {
        for (int b = 0; b < 2; b++) {
            int base = tid * 32;
            uint32_t m = 0;
            int local = 0;
#pragma unroll 8
            for (int q = 0; q < 32; q++) {
                int a = prof[b * NN + base + q] > LEAK;
                m |= ((uint32_t)a) << q;
                local += a;
            }
            int lane = tid & 31, wid = tid >> 5;
            int inc = local;
#pragma unroll
            for (int d = 1; d < 32; d <<= 1) {
                int v = __shfl_up_sync(~0u, inc, d);
                if (lane >= d) inc += v;
            }
            if (lane == 31) wsum[wid] = inc;
            __syncthreads();
            if (wid == 0 && lane < 8) {
                int v = wsum[lane];
#pragma unroll
                for (int d = 1; d < 8; d <<= 1) {
                    int u = __shfl_up_sync(0xffu, v, d);
                    if (lane >= d) v += u;
                }
                wsum[lane] = v;
            }
            __syncthreads();
            int excl = inc - local + (wid > 0 ? wsum[wid - 1] : 0);
            for (int q = 0; q < 32; q++)
                if ((m >> q) & 1) g_idx[b][excl++] = base + q;
            if (tid == 255) {
                g_cnt[b] = excl;
                for (int p = excl; p < ((excl + 63) & ~63); p++) g_idx[b][p] = -1;
            }
            __syncthreads();
        }
        return;
    }

    int row0 = blockIdx.x * 16;
    for (int i = tid; i < 4096; i += 256) {
        int c = i & 63, e = i >> 6;
        Wt[c * 68 + e] = W[e * 64 + c];
    }
    for (int i = tid; i < 1024; i += 256) Ur[i] = U[row0 * 64 + i];
    __syncthreads();
    int c = tid & 63, rq = tid >> 6;
    float acc[4] = {0.f, 0.f, 0.f, 0.f};
    const float4* wt4 = (const float4*)(Wt + c * 68);
#pragma unroll
    for (int e4 = 0; e4 < 16; e4++) {
        float4 wv = wt4[e4];
#pragma unroll
        for (int q = 0; q < 4; q++) {
            float4 uv = *(const float4*)(Ur + (rq + 4 * q) * 64 + e4 * 4);
            acc[q] += uv.x * wv.x + uv.y * wv.y + uv.z * wv.z + uv.w * wv.w;
        }
    }
#pragma unroll
    for (int q = 0; q < 4; q++) {
        int r = rq + 4 * q, row = row0 + r;
        __nv_bfloat16 h, lo;
        split2(Ur[r * 64 + c], h, lo);
        gUh[row * 64 + c] = h;
        gUl[row * 64 + c] = lo;
        split2(acc[q], h, lo);
        gVh[row * 64 + c] = h;
        gVl[row * 64 + c] = lo;
    }
}

// ---------------- prep 2: per-batch compacted V + gated E tiles ----------------
__global__ void __launch_bounds__(256) prep_effV(const float* __restrict__ S,
                                                 const float* __restrict__ prof) {
    int b = blockIdx.x >> 7, c = blockIdx.x & 127, tid = threadIdx.x;
    int nt = (g_cnt[b] + 63) >> 6;
    if (c >= nt) return;
    __shared__ float es[64 * 65];   // [i][d]
    __shared__ int sidx[64];
    __shared__ float sg[64];
    if (tid < 64) {
        int gi = g_idx[b][c * 64 + tid];
        sidx[tid] = gi;
        float g0 = 0.f;
        if (gi >= 0) {
            g0 = prof[b * NN + gi] - LEAK;
            g0 = g0 > 0.f ? g0 : 0.f;
        }
        sg[tid] = g0;
    }
    __syncthreads();
    for (int idx = tid; idx < 4096; idx += 256) {
        int r = idx >> 6, d = idx & 63;
        int gi = sidx[r];
        es[r * 65 + d] = (gi >= 0) ? S[((size_t)b * NN + gi) * 64 + d] * sg[r] : 0.f;
    }
    for (int idx = tid; idx < 2048; idx += 256) {
        int r = idx >> 5, k2 = idx & 31;
        int gi = sidx[r];
        uint32_t vh = 0u, vl = 0u;
        if (gi >= 0) {
            vh = ((const uint32_t*)gVh)[gi * 32 + k2];
            vl = ((const uint32_t*)gVl)[gi * 32 + k2];
        }
        ((uint32_t*)gVch[b])[(c * 64 + r) * 32 + k2] = vh;
        ((uint32_t*)gVcl[b])[(c * 64 + r) * 32 + k2] = vl;
    }
    __syncthreads();
    int base = c * 4096;
    for (int idx = tid; idx < 4096; idx += 256) {
        int d = idx >> 6, r = idx & 63;
        float x = es[r * 65 + d];
        __nv_bfloat16 h, lo;
        split2(x, h, lo);
        gEh[b][base + d * 64 + r] = h;
        gEl[b][base + d * 64 + r] = lo;
    }
}

// ---------------- main: per-(j-tile, batch) CTA, 2 CTAs/SM ----------------
#define SM_U 0u
#define SM_STG 18432u
#define STG_SZ 37120u   // Vh 9216 | Vl 9216 | Eh 9216 | El 9216 | idx 256
#define SM_TOTAL (18432u + 2u * 37120u)   // 92672

__device__ __forceinline__ void stage_load(uint32_t stg, int b, int t, int tid) {
#pragma unroll
    for (int idx = tid; idx < 1024; idx += 256) {
        int h = idx >> 9, rem = idx & 511, r = rem >> 3, c = rem & 7;
        uint32_t dst = stg + h * 9216u + r * 144u + c * 16u;
        const char* src = (const char*)(h ? gVcl[b] : gVch[b]) +
                          ((size_t)t * 4096 + r * 64 + c * 8) * 2;
        CP16(dst, src);
    }
#pragma unroll
    for (int idx = tid; idx < 1024; idx += 256) {
        int h = idx >> 9, rem = idx & 511, r = rem >> 3, c = rem & 7;
        uint32_t dst = stg + 18432u + h * 9216u + r * 144u + c * 16u;
        const char* src = (const char*)(h ? gEl[b] : gEh[b]) +
                          ((size_t)t * 4096 + r * 64 + c * 8) * 2;
        CP16(dst, src);
    }
    if (tid < 16)
        CP16(stg + 36864u + tid * 16u, (const char*)(g_idx[b] + t * 64) + tid * 16);
}

__global__ void __launch_bounds__(256, 2) dyadic_mma(const float* __restrict__ S,
                                                     const float* __restrict__ bias_p,
                                                     float* __restrict__ out) {
    extern __shared__ char sm[];
    const uint32_t sb = smem_u32(sm);
    const int tid = threadIdx.x, w = tid >> 5, lane = tid & 31;
    const int jc = blockIdx.x >> 1, b = blockIdx.x & 1;
    const float bias = bias_p[0];
    const int nt = (g_cnt[b] + 63) >> 6;

    const int g = lane >> 2, tig = lane & 3;
    const int a_r = lane & 15;
    const int a_c = (lane & 16) ? 8 : 0;
    const int b_r = (lane & 7) + ((lane & 16) ? 8 : 0);
    const int b_c = (lane & 8) ? 8 : 0;

    const int mj = w & 3;   // j slice [16*mj, +16)
    const int nw = w >> 2;  // i slice [32*nw, +32)

    // stage resident U tile
    {
        const uint4* sh = (const uint4*)gUh + jc * 512;
        const uint4* sl = (const uint4*)gUl + jc * 512;
        for (int idx = tid; idx < 512; idx += 256) {
            int r = idx >> 3, c = idx & 7;
            *(uint4*)(sm + SM_U + r * 144 + c * 16) = sh[idx];
            *(uint4*)(sm + SM_U + 9216 + r * 144 + c * 16) = sl[idx];
        }
    }

    float d2[8][4];
#pragma unroll
    for (int nb = 0; nb < 8; nb++)
#pragma unroll
        for (int q = 0; q < 4; q++) d2[nb][q] = 0.f;

    if (nt > 0) {
        stage_load(sb + SM_STG, b, 0, tid);
        CP_COMMIT();
        __syncthreads();  // U visible

        // hoist loop-invariant U A-fragments
        uint32_t uah[4][4], ual[4][4];
        {
            const uint32_t ua = sb + SM_U + (16 * mj + a_r) * 144 + a_c * 2;
#pragma unroll
            for (int ks = 0; ks < 4; ks++) {
                LDSM4(uah[ks][0], uah[ks][1], uah[ks][2], uah[ks][3], ua + ks * 32);
                LDSM4(ual[ks][0], ual[ks][1], ual[ks][2], ual[ks][3], ua + 9216u + ks * 32);
            }
        }

        for (int t = 0; t < nt; t++) {
            const uint32_t stg = sb + SM_STG + (uint32_t)(t & 1) * STG_SZ;

            CP_WAIT0();
            __syncthreads();  // stage t visible; prior reads of other buffer done

            if (t + 1 < nt) {
                stage_load(sb + SM_STG + (uint32_t)((t + 1) & 1) * STG_SZ, b, t + 1, tid);
                CP_COMMIT();
            }

            // ---- GEMM1: C[16j x 32i], 3-pass ----
            float c1[4][4];
#pragma unroll
            for (int nb = 0; nb < 4; nb++)
#pragma unroll
                for (int q = 0; q < 4; q++) c1[nb][q] = 0.f;

            const uint32_t vbh = stg + (32 * nw + b_r) * 144 + b_c * 2;
#pragma unroll
            for (int ks = 0; ks < 4; ks++) {
                uint32_t bh[8], bl[8];
#pragma unroll
                for (int p = 0; p < 2; p++) {
                    LDSM4(bh[4 * p], bh[4 * p + 1], bh[4 * p + 2], bh[4 * p + 3],
                          vbh + p * 16 * 144 + ks * 32);
                    LDSM4(bl[4 * p], bl[4 * p + 1], bl[4 * p + 2], bl[4 * p + 3],
                          vbh + 9216u + p * 16 * 144 + ks * 32);
                }
#pragma unroll
                for (int nb = 0; nb < 4; nb++) {
                    int bi = (nb >> 1) * 4 + (nb & 1) * 2;
                    MMA_BF16(c1[nb], uah[ks][0], uah[ks][1], uah[ks][2], uah[ks][3],
                             bh[bi], bh[bi + 1]);
                    MMA_BF16(c1[nb], uah[ks][0], uah[ks][1], uah[ks][2], uah[ks][3],
                             bl[bi], bl[bi + 1]);
                    MMA_BF16(c1[nb], ual[ks][0], ual[ks][1], ual[ks][2], ual[ks][3],
                             bh[bi], bh[bi + 1]);
                }
            }

            // ---- epilogue in registers: sigmoid + mask + split + pack ----
            uint32_t pah[2][4], pal[2][4];
#pragma unroll
            for (int nb = 0; nb < 4; nb++) {
                uint32_t i0, i1;
                asm volatile("ld.shared.v2.u32 {%0,%1}, [%2];" : "=r"(i0), "=r"(i1)
                             : "r"(stg + 36864u + (uint32_t)(32 * nw + 8 * nb + 2 * tig) * 4u));
                float tv[4];
#pragma unroll
                for (int q = 0; q < 4; q++) {
                    float x = c1[nb][q] + bias;
                    float s = __fdividef(1.f, 1.f + __expf(-x));
                    int gi = (int)((q & 1) ? i1 : i0);
                    int jg = 64 * jc + 16 * mj + g + ((q & 2) ? 8 : 0);
                    if (gi == jg) s = 0.f;
                    tv[q] = s;
                }
                __nv_bfloat16 h0, l0, h1, l1, h2, l2, h3, l3;
                split2(tv[0], h0, l0); split2(tv[1], h1, l1);
                split2(tv[2], h2, l2); split2(tv[3], h3, l3);
                int ks2 = nb >> 1, ai = 2 * (nb & 1);
                pah[ks2][ai]     = (uint32_t)__bfloat16_as_ushort(h0) | ((uint32_t)__bfloat16_as_ushort(h1) << 16);
                pah[ks2][ai + 1] = (uint32_t)__bfloat16_as_ushort(h2) | ((uint32_t)__bfloat16_as_ushort(h3) << 16);
                pal[ks2][ai]     = (uint32_t)__bfloat16_as_ushort(l0) | ((uint32_t)__bfloat16_as_ushort(l1) << 16);
                pal[ks2][ai + 1] = (uint32_t)__bfloat16_as_ushort(l2) | ((uint32_t)__bfloat16_as_ushort(l3) << 16);
            }

            // ---- GEMM2: D2[16j x 64d] += P^T . E_b, K = warp's 32 i, 3-pass ----
            const uint32_t eb = stg + 18432u + b_r * 144u + b_c * 2u + (uint32_t)(64 * nw);
#pragma unroll
            for (int ks2 = 0; ks2 < 2; ks2++) {
#pragma unroll
                for (int p = 0; p < 4; p++) {
                    uint32_t bh[4], bl[4];
                    uint32_t ea = eb + p * 16 * 144 + ks2 * 32;
                    LDSM4(bh[0], bh[1], bh[2], bh[3], ea);
                    LDSM4(bl[0], bl[1], bl[2], bl[3], ea + 9216u);
#pragma unroll
                    for (int blk = 0; blk < 2; blk++) {
                        int nb = 2 * p + blk;
                        MMA_BF16(d2[nb], pah[ks2][0], pah[ks2][1], pah[ks2][2], pah[ks2][3],
                                 bh[2 * blk], bh[2 * blk + 1]);
                        MMA_BF16(d2[nb], pah[ks2][0], pah[ks2][1], pah[ks2][2], pah[ks2][3],
                                 bl[2 * blk], bl[2 * blk + 1]);
                        MMA_BF16(d2[nb], pal[ks2][0], pal[ks2][1], pal[ks2][2], pal[ks2][3],
                                 bh[2 * blk], bh[2 * blk + 1]);
                    }
                }
            }
        }
    }

    // ---- cross-warp K reduction (nw pairs) + store out (batch b rows only) ----
    __syncthreads();
    float* red = (float*)(sm + SM_STG);
    if (nw == 1) {
#pragma unroll
        for (int nb = 0; nb < 8; nb++)
#pragma unroll
            for (int q = 0; q < 4; q++)
                red[(mj * 32 + nb * 4 + q) * 32 + lane] = d2[nb][q];
    }
    __syncthreads();
    if (nw == 0) {
#pragma unroll
        for (int nb = 0; nb < 8; nb++)
#pragma unroll
            for (int q = 0; q < 4; q++)
                d2[nb][q] += red[(mj * 32 + nb * 4 + q) * 32 + lane];
#pragma unroll
        for (int nb = 0; nb < 8; nb++) {
            int d = 8 * nb + 2 * tig;
#pragma unroll
            for (int half = 0; half < 2; half++) {
                int j = 64 * jc + 16 * mj + g + 8 * half;
                size_t off = ((size_t)(b * NN + j)) * 64 + d;
                float2 sv = *(const float2*)(S + off);
                float2 ov;
                ov.x = sv.x + d2[nb][2 * half + 0];
                ov.y = sv.y + d2[nb][2 * half + 1];
                *(float2*)(out + off) = ov;
            }
        }
    }
}

extern "C" void kernel_launch(void* const* d_in, const int* in_sizes, int n_in,
                              void* d_out, int out_size) {
    const float* S    = (const float*)d_in[0];  // task_states   [2,8192,64]
    const float* prof = (const float*)d_in[1];  // proficiency   [2,8192]
    const float* U    = (const float*)d_in[2];  // task_embeddings [8192,64]
    const float* W    = (const float*)d_in[3];  // bilinear_weight [1,64,64]
    const float* bias = (const float*)d_in[4];  // bilinear_bias  [1]
    float* out = (float*)d_out;

    prep_se<<<513, 256>>>(U, W, prof);
    prep_effV<<<256, 256>>>(S, prof);

    cudaFuncSetAttribute(dyadic_mma, cudaFuncAttributeMaxDynamicSharedMemorySize, SM_TOTAL);
    dyadic_mma<<<256, 256, SM_TOTAL>>>(S, bias, out);
}